// round 15
// baseline (speedup 1.0000x reference)
#include <cuda_runtime.h>
#include <cuda_bf16.h>
#include <cstdint>

// ============================ problem constants =============================
static constexpr int NTOK = 8192;
static constexpr int DIM  = 1024;
static constexpr int VOC  = 32000;
static constexpr int TM = 128;            // tokens per CTA tile
static constexpr int TN = 128;            // vocab per CTA tile (2 CTAs/SM)
static constexpr int TK = 64;             // K elems per chunk (128B rows)
static constexpr int KCHUNKS = DIM / TK;  // 16
static constexpr int STAGES  = 3;
static constexpr int VT = VOC / TN;       // 250
static constexpr int MT = NTOK / TM;      // 64
static constexpr int LOSS_BLOCKS = 256;

// ============================ device scratch ================================
__device__ __align__(128) __nv_bfloat16 g_Xbf[(size_t)NTOK * DIM];   // 16 MB
__device__ __align__(128) __nv_bfloat16 g_Wbf[(size_t)VOC * DIM];    // 64 MB
__device__ __align__(128) float g_S1p[(size_t)VT * NTOK];            // 8 MB
__device__ __align__(128) float g_S2p[(size_t)VT * NTOK];            // 8 MB
__device__ __align__(128) float g_psum[LOSS_BLOCKS];
__device__ int g_tflag;          // 1 = target is int64, 0 = int32
__device__ int g_bcount;         // loss-block completion counter
__device__ int g_xdone;          // X-convert completion count (== MT when ready)
__device__ int g_wready[VT];     // per-vt W-convert ready flags

// ============================ helpers =======================================
__device__ __forceinline__ uint32_t smem_u32(const void* p) {
    uint32_t a;
    asm("{ .reg .u64 t; cvta.to.shared.u64 t, %1; cvt.u32.u64 %0, t; }" : "=r"(a) : "l"(p));
    return a;
}
#define CP_ASYNC16(dst, src) \
    asm volatile("cp.async.cg.shared.global [%0], [%1], 16;" :: "r"(dst), "l"(src) : "memory")
#define CP_COMMIT() asm volatile("cp.async.commit_group;" ::: "memory")
#define CP_WAIT(n)  asm volatile("cp.async.wait_group %0;" :: "n"(n) : "memory")

__device__ __forceinline__ void ldm_x4(uint32_t* r, uint32_t addr) {
    asm volatile("ldmatrix.sync.aligned.m8n8.x4.shared.b16 {%0,%1,%2,%3}, [%4];"
        : "=r"(r[0]), "=r"(r[1]), "=r"(r[2]), "=r"(r[3]) : "r"(addr));
}
__device__ __forceinline__ void mma16816(float* c, const uint32_t* a, uint32_t b0, uint32_t b1) {
    asm volatile(
        "mma.sync.aligned.m16n8k16.row.col.f32.bf16.bf16.f32 "
        "{%0,%1,%2,%3}, {%4,%5,%6,%7}, {%8,%9}, {%0,%1,%2,%3};"
        : "+f"(c[0]), "+f"(c[1]), "+f"(c[2]), "+f"(c[3])
        : "r"(a[0]), "r"(a[1]), "r"(a[2]), "r"(a[3]), "r"(b0), "r"(b1));
}

// exp via MUFU: exp(x) = ex2(x * log2(e)); rel err ~2^-22
static constexpr float LOG2E = 1.4426950408889634f;
__device__ __forceinline__ float fexp2(float x) {
    float r;
    asm("ex2.approx.f32 %0, %1;" : "=f"(r) : "f"(x));
    return r;
}
__device__ __forceinline__ int read_target(const void* tgt, int i, int flag) {
    return flag ? (int)(((const long long*)tgt)[i]) : ((const int*)tgt)[i];
}

// ============================ kernel 1: GEMM + fused convert + softmax =======
// 2 CTAs per SM. Conversion duties (overlapped with machine fill):
//   vt==0 CTAs: convert X rows [mt*128, mt*128+128), signal g_xdone.
//   mt==0 CTAs: convert W rows [vt*128, vt*128+128), signal g_wready[vt].
//   (0,0):      also dtype-detect. Dispatch is bid-ordered (bid = mt + 64*vt),
//   so each vt's converter is resident no later than its consumers.
static constexpr int SM_BIAS   = 0;                       // 128 floats
static constexpr int SM_SRED1  = 512;                     // 8*64 floats
static constexpr int SM_SRED2  = 2560;
static constexpr int SM_STAGE0 = 5120;                    // 1024-aligned
static constexpr int A_BYTES   = TM * 128;                // 16384
static constexpr int STAGE_BYTES = (TM + TN) * 128;       // 32768
static constexpr int GEMM_SMEM = SM_STAGE0 + STAGES * STAGE_BYTES;  // 103424

__device__ __forceinline__ void load_chunk(uint32_t stage_base, int tid, int m0, int v0, int kc) {
    const __nv_bfloat16* Asrc = g_Xbf + (size_t)m0 * DIM + kc * TK;
    const __nv_bfloat16* Bsrc = g_Wbf + (size_t)v0 * DIM + kc * TK;
#pragma unroll
    for (int i = 0; i < 8; i++) {
        int g = tid + i * 256;                 // 0..2047
        if (g < 1024) {                        // A: 128 rows x 8 x 16B
            int row = g >> 3, c16 = g & 7;
            uint32_t off = (uint32_t)(row * 128) + (((uint32_t)c16 * 16) ^ (((uint32_t)row & 7) << 4));
            CP_ASYNC16(stage_base + off, Asrc + (size_t)row * DIM + c16 * 8);
        } else {                               // B: 128 rows x 8 x 16B
            int g2 = g - 1024;
            int row = g2 >> 3, c16 = g2 & 7;
            uint32_t off = (uint32_t)(row * 128) + (((uint32_t)c16 * 16) ^ (((uint32_t)row & 7) << 4));
            CP_ASYNC16(stage_base + A_BYTES + off, Bsrc + (size_t)row * DIM + c16 * 8);
        }
    }
}

__global__ __launch_bounds__(256, 2) void gemm_kernel(const float* __restrict__ bias,
                                                      const float* __restrict__ x,
                                                      const float* __restrict__ w,
                                                      const void* __restrict__ tgt) {
    extern __shared__ char smem[];
    uint32_t sb = smem_u32(smem);
    int tid = threadIdx.x;
    int lane = tid & 31, wid = tid >> 5;
    int wr = wid >> 2, wc = wid & 3;           // warp row (M: 2x64), warp col (N: 4x32)
    int mt = blockIdx.x, vt = blockIdx.y;
    int m0 = mt * TM, v0 = vt * TN;

    float* biasS = (float*)(smem + SM_BIAS);
    float* sdS1  = (float*)(smem + SM_SRED1);  // [8 warps][64 rows]
    float* sdS2  = (float*)(smem + SM_SRED2);

    // ---- conversion duties (overlap with fill of the rest of the grid) ----
    if (mt == 0 && vt == 0) {                  // dtype detect (deterministic)
        __shared__ int bad;
        if (tid == 0) bad = 0;
        __syncthreads();
        const unsigned long long* p = (const unsigned long long*)tgt;
        for (int i = tid; i < NTOK / 2; i += 256)
            if (p[i] >= (unsigned long long)VOC) bad = 1;
        __syncthreads();
        if (tid == 0) g_tflag = bad ? 0 : 1;
    }
    if (vt == 0) {                             // convert X slice [m0, m0+128)
        const float4* src = (const float4*)x + (size_t)m0 * (DIM / 4);
        __nv_bfloat162* dst = (__nv_bfloat162*)(g_Xbf + (size_t)m0 * DIM);
        for (int k = tid; k < TM * (DIM / 4); k += 256) {
            float4 v = src[k];
            dst[2 * k]     = __floats2bfloat162_rn(v.x, v.y);
            dst[2 * k + 1] = __floats2bfloat162_rn(v.z, v.w);
        }
        __threadfence();
        __syncthreads();
        if (tid == 0) atomicAdd(&g_xdone, 1);
    }
    if (mt == 0) {                             // convert W slice [v0, v0+128)
        const float4* src = (const float4*)w + (size_t)v0 * (DIM / 4);
        __nv_bfloat162* dst = (__nv_bfloat162*)(g_Wbf + (size_t)v0 * DIM);
        for (int k = tid; k < TN * (DIM / 4); k += 256) {
            float4 v = src[k];
            dst[2 * k]     = __floats2bfloat162_rn(v.x, v.y);
            dst[2 * k + 1] = __floats2bfloat162_rn(v.z, v.w);
        }
        __threadfence();
        __syncthreads();
        if (tid == 0) atomicExch(&g_wready[vt], 1);
    }

    if (tid < TN) biasS[tid] = bias[v0 + tid];

    // ---- wait for required inputs (one polling thread, then block sync) ----
    if (tid == 0) {
        while (atomicAdd(&g_xdone, 0) < MT) {}
        while (atomicAdd(&g_wready[vt], 0) == 0) {}
    }
    __syncthreads();

    // ldmatrix per-lane geometry (offsets within a stage)
    uint32_t xm    = ((uint32_t)lane & 7) << 4;
    int arow  = wr * 64 + (lane & 7) + ((lane >> 3) & 1) * 8;
    uint32_t acolt = ((uint32_t)(lane >> 4) & 1) * 16;
    int brow  = wc * 32 + ((lane >> 4) & 1) * 8 + (lane & 7);
    uint32_t bcolt = ((uint32_t)(lane >> 3) & 1) * 16;

    float acc[4][4][4];                        // 64 accums/thread
#pragma unroll
    for (int i = 0; i < 4; i++)
#pragma unroll
        for (int j = 0; j < 4; j++)
#pragma unroll
            for (int k = 0; k < 4; k++) acc[i][j][k] = 0.0f;

    // prologue: fill stages 0..1
#pragma unroll
    for (int s = 0; s < STAGES - 1; s++) {
        load_chunk(sb + SM_STAGE0 + s * STAGE_BYTES, tid, m0, v0, s);
        CP_COMMIT();
    }

    int st_c = 0, st_l = STAGES - 1;           // rotating stage indices
    for (int kc = 0; kc < KCHUNKS; kc++) {
        CP_WAIT(1);
        __syncthreads();
        if (kc + STAGES - 1 < KCHUNKS)
            load_chunk(sb + SM_STAGE0 + st_l * STAGE_BYTES, tid, m0, v0, kc + STAGES - 1);
        CP_COMMIT();   // fixed group cadence
        if (++st_l == STAGES) st_l = 0;

        uint32_t abase = sb + SM_STAGE0 + st_c * STAGE_BYTES;
        uint32_t bbase = abase + A_BYTES;
        if (++st_c == STAGES) st_c = 0;
#pragma unroll
        for (int s = 0; s < 4; s++) {          // 4 k16-steps per 64-elem chunk
            uint32_t a[4][4], b[2][4];
#pragma unroll
            for (int ma = 0; ma < 4; ma++)
                ldm_x4(a[ma], abase + (uint32_t)((arow + ma * 16) * 128) + (((uint32_t)(s * 32) + acolt) ^ xm));
#pragma unroll
            for (int p = 0; p < 2; p++)
                ldm_x4(b[p], bbase + (uint32_t)((brow + p * 16) * 128) + (((uint32_t)(s * 32) + bcolt) ^ xm));
#pragma unroll
            for (int ma = 0; ma < 4; ma++)
#pragma unroll
                for (int na = 0; na < 4; na++)
                    mma16816(acc[ma][na], a[ma], b[na >> 1][(na & 1) * 2], b[na >> 1][(na & 1) * 2 + 1]);
        }
    }
    __syncthreads();

    // ---- fused epilogue: bias + MUFU exp + row reduction ----
#pragma unroll
    for (int ma = 0; ma < 4; ma++) {
        float s1lo = 0.f, s2lo = 0.f, s1hi = 0.f, s2hi = 0.f;
#pragma unroll
        for (int na = 0; na < 4; na++) {
            int c0 = wc * 32 + na * 8 + 2 * (lane & 3);
            float b0 = biasS[c0], b1 = biasS[c0 + 1];
            float v;
            v = acc[ma][na][0] + b0; s2lo += v; s1lo += fexp2(v * LOG2E);
            v = acc[ma][na][1] + b1; s2lo += v; s1lo += fexp2(v * LOG2E);
            v = acc[ma][na][2] + b0; s2hi += v; s1hi += fexp2(v * LOG2E);
            v = acc[ma][na][3] + b1; s2hi += v; s1hi += fexp2(v * LOG2E);
        }
#pragma unroll
        for (int o = 1; o <= 2; o <<= 1) {
            s1lo += __shfl_xor_sync(0xFFFFFFFFu, s1lo, o);
            s2lo += __shfl_xor_sync(0xFFFFFFFFu, s2lo, o);
            s1hi += __shfl_xor_sync(0xFFFFFFFFu, s1hi, o);
            s2hi += __shfl_xor_sync(0xFFFFFFFFu, s2hi, o);
        }
        if ((lane & 3) == 0) {
            int rloc = ma * 16 + (lane >> 2);
            sdS1[wid * 64 + rloc]     = s1lo;
            sdS2[wid * 64 + rloc]     = s2lo;
            sdS1[wid * 64 + rloc + 8] = s1hi;
            sdS2[wid * 64 + rloc + 8] = s2hi;
        }
    }
    __syncthreads();
    if (tid < TM) {
        int wrow = tid >> 6, rin = tid & 63;   // wrow: which warp-row (wr)
        float S1 = 0.f, S2 = 0.f;
#pragma unroll
        for (int w4 = 0; w4 < 4; w4++) {       // reduce across the 4 warp-cols
            S1 += sdS1[(wrow * 4 + w4) * 64 + rin];
            S2 += sdS2[(wrow * 4 + w4) * 64 + rin];
        }
        g_S1p[(size_t)vt * NTOK + m0 + tid] = S1;
        g_S2p[(size_t)vt * NTOK + m0 + tid] = S2;
    }
}

// ============================ kernel 2: tlogit + loss + final reduce =========
// block = (32 lanes, 32 warps) = 1024 threads; grid = 256 blocks of 32 tokens.
// Last block also resets the cross-launch flags for the next graph replay.
__global__ __launch_bounds__(1024) void loss_kernel(const void* __restrict__ tgt,
                                                    const float* __restrict__ bias,
                                                    float* __restrict__ out) {
    __shared__ float sh1[32][32];
    __shared__ float sh2[32][32];
    __shared__ float sh_tl[32];
    __shared__ int   islast;
    int tx = threadIdx.x;          // lane / token-in-block
    int ty = threadIdx.y;          // warp / vt-split
    int flag = g_tflag;

    // ---- Phase A: target logit for token (blockIdx.x*32 + ty), warp-per-token
    {
        int i = blockIdx.x * 32 + ty;
        int t = read_target(tgt, i, flag);
        const uint4* xv = (const uint4*)(g_Xbf + (size_t)i * DIM);   // 8 bf16 per uint4
        const uint4* wv = (const uint4*)(g_Wbf + (size_t)t * DIM);
        float acc = 0.0f;
#pragma unroll
        for (int j = 0; j < 4; j++) {
            uint4 av = xv[tx + 32 * j];
            uint4 bv = wv[tx + 32 * j];
            const __nv_bfloat162* a2 = (const __nv_bfloat162*)&av;
            const __nv_bfloat162* b2 = (const __nv_bfloat162*)&bv;
#pragma unroll
            for (int q = 0; q < 4; q++) {
                float2 af = __bfloat1622float2(a2[q]);
                float2 bf = __bfloat1622float2(b2[q]);
                acc = fmaf(af.x, bf.x, acc);
                acc = fmaf(af.y, bf.y, acc);
            }
        }
#pragma unroll
        for (int o = 16; o; o >>= 1) acc += __shfl_xor_sync(0xFFFFFFFFu, acc, o);
        if (tx == 0) sh_tl[ty] = acc + bias[t];
    }

    // ---- Phase B: vt-split partial sums (token tx, split ty)
    int i = blockIdx.x * 32 + tx;
    int vt0 = ty * 8;
    int vt1 = (vt0 + 8 < VT) ? vt0 + 8 : VT;   // last split (ty=31): 248..249
    float s1 = 0.0f, s2 = 0.0f;
#pragma unroll 8
    for (int vt = vt0; vt < vt1; vt++) {
        s1 += g_S1p[(size_t)vt * NTOK + i];
        s2 += g_S2p[(size_t)vt * NTOK + i];
    }
    sh1[ty][tx] = s1;
    sh2[ty][tx] = s2;
    __syncthreads();

    // ---- Phase C: per-token loss + deterministic global reduce
    if (ty == 0) {                 // one warp (tx = token 0..31)
        float S1 = 0.0f, S2 = 0.0f;
#pragma unroll
        for (int s = 0; s < 32; s++) { S1 += sh1[s][tx]; S2 += sh2[s][tx]; }
        int t = read_target(tgt, i, flag);
        float l = (t != 0)
            ? (logf(S1) - 0.9f * sh_tl[tx] - (0.1f / (float)VOC) * S2) : 0.0f;
        // fixed-order warp tree over the 32 tokens of this block
#pragma unroll
        for (int o = 16; o; o >>= 1) l += __shfl_xor_sync(0xFFFFFFFFu, l, o);
        if (tx == 0) {
            g_psum[blockIdx.x] = l;
            __threadfence();
            int old = atomicAdd(&g_bcount, 1);
            islast = (old == LOSS_BLOCKS - 1) ? 1 : 0;
        }
        __syncwarp();
        if (islast) {              // last block: reduce 256 partials, fixed order
            float a = 0.0f;
#pragma unroll
            for (int q = 0; q < LOSS_BLOCKS / 32; q++)   // each lane: 8 slots
                a += g_psum[tx * (LOSS_BLOCKS / 32) + q];
#pragma unroll
            for (int o = 16; o; o >>= 1) a += __shfl_xor_sync(0xFFFFFFFFu, a, o);
            if (tx == 0) out[0] = a;
        }
    }
    // ---- reset cross-launch flags for the next graph replay (last block only)
    __syncthreads();
    if (islast) {
        int tid1d = ty * 32 + tx;
        for (int q = tid1d; q < VT; q += 1024) g_wready[q] = 0;
        if (tid1d == 0) { g_xdone = 0; g_bcount = 0; }
    }
}

// ============================ launch =========================================
extern "C" void kernel_launch(void* const* d_in, const int* in_sizes, int n_in,
                              void* d_out, int out_size) {
    const float* x    = (const float*)d_in[0];
    const void*  tgt  = d_in[1];
    const float* w    = (const float*)d_in[2];
    const float* bias = (const float*)d_in[3];

    cudaFuncSetAttribute(gemm_kernel, cudaFuncAttributeMaxDynamicSharedMemorySize, GEMM_SMEM);

    dim3 g(MT, VT);   // mt fast-varying: X tiles (16MB) stay resident in L2
    gemm_kernel<<<g, 256, GEMM_SMEM>>>(bias, x, w, tgt);   // fused convert + GEMM

    loss_kernel<<<LOSS_BLOCKS, dim3(32, 32)>>>(tgt, bias, (float*)d_out);
}

// round 16
// speedup vs baseline: 1.9050x; 1.9050x over previous
#include <cuda_runtime.h>
#include <cuda_bf16.h>
#include <cstdint>

// ============================ problem constants =============================
static constexpr int NTOK = 8192;
static constexpr int DIM  = 1024;
static constexpr int VOC  = 32000;
static constexpr int TM = 128;            // tokens per CTA tile
static constexpr int TN = 128;            // vocab per CTA tile (2 CTAs/SM)
static constexpr int TK = 64;             // K elems per chunk (128B rows)
static constexpr int KCHUNKS = DIM / TK;  // 16
static constexpr int STAGES  = 3;
static constexpr int VT = VOC / TN;       // 250
static constexpr int MT = NTOK / TM;      // 64
static constexpr int LOSS_BLOCKS = 256;
static constexpr int W_HEAD = 45;         // W tiles converted by prep_kernel
static constexpr int W_LEAD = 20;         // look-ahead distance (vt) for in-GEMM converters

// ============================ device scratch ================================
__device__ __align__(128) __nv_bfloat16 g_Xbf[(size_t)NTOK * DIM];   // 16 MB
__device__ __align__(128) __nv_bfloat16 g_Wbf[(size_t)VOC * DIM];    // 64 MB
__device__ __align__(128) float g_S1p[(size_t)VT * NTOK];            // 8 MB
__device__ __align__(128) float g_S2p[(size_t)VT * NTOK];            // 8 MB
__device__ __align__(128) float g_psum[LOSS_BLOCKS];
__device__ int g_tflag;          // 1 = target is int64, 0 = int32
__device__ int g_bcount;         // loss-block completion counter
__device__ int g_wready[VT];     // per-vt W-convert ready flags (tiles >= W_HEAD)

// ============================ helpers =======================================
__device__ __forceinline__ uint32_t smem_u32(const void* p) {
    uint32_t a;
    asm("{ .reg .u64 t; cvta.to.shared.u64 t, %1; cvt.u32.u64 %0, t; }" : "=r"(a) : "l"(p));
    return a;
}
#define CP_ASYNC16(dst, src) \
    asm volatile("cp.async.cg.shared.global [%0], [%1], 16;" :: "r"(dst), "l"(src) : "memory")
#define CP_COMMIT() asm volatile("cp.async.commit_group;" ::: "memory")
#define CP_WAIT(n)  asm volatile("cp.async.wait_group %0;" :: "n"(n) : "memory")

__device__ __forceinline__ void ldm_x4(uint32_t* r, uint32_t addr) {
    asm volatile("ldmatrix.sync.aligned.m8n8.x4.shared.b16 {%0,%1,%2,%3}, [%4];"
        : "=r"(r[0]), "=r"(r[1]), "=r"(r[2]), "=r"(r[3]) : "r"(addr));
}
__device__ __forceinline__ void mma16816(float* c, const uint32_t* a, uint32_t b0, uint32_t b1) {
    asm volatile(
        "mma.sync.aligned.m16n8k16.row.col.f32.bf16.bf16.f32 "
        "{%0,%1,%2,%3}, {%4,%5,%6,%7}, {%8,%9}, {%0,%1,%2,%3};"
        : "+f"(c[0]), "+f"(c[1]), "+f"(c[2]), "+f"(c[3])
        : "r"(a[0]), "r"(a[1]), "r"(a[2]), "r"(a[3]), "r"(b0), "r"(b1));
}

// exp via MUFU: exp(x) = ex2(x * log2(e)); rel err ~2^-22
static constexpr float LOG2E = 1.4426950408889634f;
__device__ __forceinline__ float fexp2(float x) {
    float r;
    asm("ex2.approx.f32 %0, %1;" : "=f"(r) : "f"(x));
    return r;
}
__device__ __forceinline__ int read_target(const void* tgt, int i, int flag) {
    return flag ? (int)(((const long long*)tgt)[i]) : ((const int*)tgt)[i];
}

// ============================ kernel 1: prep =================================
// converts ALL of X + the first W_HEAD W tiles; dtype detect; counter reset.
static constexpr size_t NX4      = (size_t)NTOK * DIM / 4;              // 2M float4
static constexpr size_t NW4HEAD  = (size_t)W_HEAD * TN * DIM / 4;       // 1.44M float4
__global__ void prep_kernel(const float* __restrict__ x, const float* __restrict__ w,
                            const void* __restrict__ tgt) {
    if (blockIdx.x == 0) {
        __shared__ int bad;
        if (threadIdx.x == 0) { bad = 0; g_bcount = 0; }
        __syncthreads();
        const unsigned long long* p = (const unsigned long long*)tgt;
        for (int i = threadIdx.x; i < NTOK / 2; i += blockDim.x)
            if (p[i] >= (unsigned long long)VOC) bad = 1;
        __syncthreads();
        if (threadIdx.x == 0) g_tflag = bad ? 0 : 1;
    }
    size_t i = (size_t)blockIdx.x * blockDim.x + threadIdx.x;
    if (i < NX4) {
        float4 v = ((const float4*)x)[i];
        ((__nv_bfloat162*)g_Xbf)[2 * i]     = __floats2bfloat162_rn(v.x, v.y);
        ((__nv_bfloat162*)g_Xbf)[2 * i + 1] = __floats2bfloat162_rn(v.z, v.w);
    } else if (i < NX4 + NW4HEAD) {
        size_t j = i - NX4;
        float4 v = ((const float4*)w)[j];
        ((__nv_bfloat162*)g_Wbf)[2 * j]     = __floats2bfloat162_rn(v.x, v.y);
        ((__nv_bfloat162*)g_Wbf)[2 * j + 1] = __floats2bfloat162_rn(v.z, v.w);
    }
}

// ============================ kernel 2: GEMM + look-ahead convert + softmax ==
// 2 CTAs per SM. CTA (mt, vt) with mt == (vt+W_LEAD)%64 and 45<=vt+W_LEAD<=249
// converts W tile vt+W_LEAD (~4 waves ahead of its consumers) before its own
// mainloop. Consumers of vt>=W_HEAD read a per-vt flag (expected already set).
static constexpr int SM_BIAS   = 0;                       // 128 floats
static constexpr int SM_SRED1  = 512;                     // 8*64 floats
static constexpr int SM_SRED2  = 2560;
static constexpr int SM_STAGE0 = 5120;                    // 1024-aligned
static constexpr int A_BYTES   = TM * 128;                // 16384
static constexpr int STAGE_BYTES = (TM + TN) * 128;       // 32768
static constexpr int GEMM_SMEM = SM_STAGE0 + STAGES * STAGE_BYTES;  // 103424

__device__ __forceinline__ void load_chunk(uint32_t stage_base, int tid, int m0, int v0, int kc) {
    const __nv_bfloat16* Asrc = g_Xbf + (size_t)m0 * DIM + kc * TK;
    const __nv_bfloat16* Bsrc = g_Wbf + (size_t)v0 * DIM + kc * TK;
#pragma unroll
    for (int i = 0; i < 8; i++) {
        int g = tid + i * 256;                 // 0..2047
        if (g < 1024) {                        // A: 128 rows x 8 x 16B
            int row = g >> 3, c16 = g & 7;
            uint32_t off = (uint32_t)(row * 128) + (((uint32_t)c16 * 16) ^ (((uint32_t)row & 7) << 4));
            CP_ASYNC16(stage_base + off, Asrc + (size_t)row * DIM + c16 * 8);
        } else {                               // B: 128 rows x 8 x 16B
            int g2 = g - 1024;
            int row = g2 >> 3, c16 = g2 & 7;
            uint32_t off = (uint32_t)(row * 128) + (((uint32_t)c16 * 16) ^ (((uint32_t)row & 7) << 4));
            CP_ASYNC16(stage_base + A_BYTES + off, Bsrc + (size_t)row * DIM + c16 * 8);
        }
    }
}

__global__ __launch_bounds__(256, 2) void gemm_kernel(const float* __restrict__ bias,
                                                      const float* __restrict__ w) {
    extern __shared__ char smem[];
    uint32_t sb = smem_u32(smem);
    int tid = threadIdx.x;
    int lane = tid & 31, wid = tid >> 5;
    int wr = wid >> 2, wc = wid & 3;           // warp row (M: 2x64), warp col (N: 4x32)
    int mt = blockIdx.x, vt = blockIdx.y;
    int m0 = mt * TM, v0 = vt * TN;

    float* biasS = (float*)(smem + SM_BIAS);
    float* sdS1  = (float*)(smem + SM_SRED1);  // [8 warps][64 rows]
    float* sdS2  = (float*)(smem + SM_SRED2);
    if (tid < TN) biasS[tid] = bias[v0 + tid];

    // ---- look-ahead W conversion (4+ waves ahead of consumers) ----
    {
        int tvt = vt + W_LEAD;
        if (tvt >= W_HEAD && tvt < VT && mt == (tvt & 63)) {
            const float4* src = (const float4*)w + (size_t)tvt * TN * (DIM / 4);
            __nv_bfloat162* dst = (__nv_bfloat162*)(g_Wbf + (size_t)tvt * TN * DIM);
            for (int k = tid; k < TN * (DIM / 4); k += 256) {
                float4 v = src[k];
                dst[2 * k]     = __floats2bfloat162_rn(v.x, v.y);
                dst[2 * k + 1] = __floats2bfloat162_rn(v.z, v.w);
            }
            __threadfence();
            __syncthreads();
            if (tid == 0) atomicExch(&g_wready[tvt], 1);
        }
    }

    // ---- wait for this tile's W data (expected already set; one plain read)
    if (vt >= W_HEAD) {
        if (tid == 0) {
            volatile int* f = &g_wready[vt];
            while (*f == 0) {}
        }
        __threadfence();
        __syncthreads();
    }

    // ldmatrix per-lane geometry (offsets within a stage)
    uint32_t xm    = ((uint32_t)lane & 7) << 4;
    int arow  = wr * 64 + (lane & 7) + ((lane >> 3) & 1) * 8;
    uint32_t acolt = ((uint32_t)(lane >> 4) & 1) * 16;
    int brow  = wc * 32 + ((lane >> 4) & 1) * 8 + (lane & 7);
    uint32_t bcolt = ((uint32_t)(lane >> 3) & 1) * 16;

    float acc[4][4][4];                        // 64 accums/thread
#pragma unroll
    for (int i = 0; i < 4; i++)
#pragma unroll
        for (int j = 0; j < 4; j++)
#pragma unroll
            for (int k = 0; k < 4; k++) acc[i][j][k] = 0.0f;

    // prologue: fill stages 0..1
#pragma unroll
    for (int s = 0; s < STAGES - 1; s++) {
        load_chunk(sb + SM_STAGE0 + s * STAGE_BYTES, tid, m0, v0, s);
        CP_COMMIT();
    }

    int st_c = 0, st_l = STAGES - 1;           // rotating stage indices
    for (int kc = 0; kc < KCHUNKS; kc++) {
        CP_WAIT(1);
        __syncthreads();
        if (kc + STAGES - 1 < KCHUNKS)
            load_chunk(sb + SM_STAGE0 + st_l * STAGE_BYTES, tid, m0, v0, kc + STAGES - 1);
        CP_COMMIT();   // fixed group cadence
        if (++st_l == STAGES) st_l = 0;

        uint32_t abase = sb + SM_STAGE0 + st_c * STAGE_BYTES;
        uint32_t bbase = abase + A_BYTES;
        if (++st_c == STAGES) st_c = 0;
#pragma unroll
        for (int s = 0; s < 4; s++) {          // 4 k16-steps per 64-elem chunk
            uint32_t a[4][4], b[2][4];
#pragma unroll
            for (int ma = 0; ma < 4; ma++)
                ldm_x4(a[ma], abase + (uint32_t)((arow + ma * 16) * 128) + (((uint32_t)(s * 32) + acolt) ^ xm));
#pragma unroll
            for (int p = 0; p < 2; p++)
                ldm_x4(b[p], bbase + (uint32_t)((brow + p * 16) * 128) + (((uint32_t)(s * 32) + bcolt) ^ xm));
#pragma unroll
            for (int ma = 0; ma < 4; ma++)
#pragma unroll
                for (int na = 0; na < 4; na++)
                    mma16816(acc[ma][na], a[ma], b[na >> 1][(na & 1) * 2], b[na >> 1][(na & 1) * 2 + 1]);
        }
    }
    __syncthreads();

    // ---- fused epilogue: bias + MUFU exp + row reduction ----
#pragma unroll
    for (int ma = 0; ma < 4; ma++) {
        float s1lo = 0.f, s2lo = 0.f, s1hi = 0.f, s2hi = 0.f;
#pragma unroll
        for (int na = 0; na < 4; na++) {
            int c0 = wc * 32 + na * 8 + 2 * (lane & 3);
            float b0 = biasS[c0], b1 = biasS[c0 + 1];
            float v;
            v = acc[ma][na][0] + b0; s2lo += v; s1lo += fexp2(v * LOG2E);
            v = acc[ma][na][1] + b1; s2lo += v; s1lo += fexp2(v * LOG2E);
            v = acc[ma][na][2] + b0; s2hi += v; s1hi += fexp2(v * LOG2E);
            v = acc[ma][na][3] + b1; s2hi += v; s1hi += fexp2(v * LOG2E);
        }
#pragma unroll
        for (int o = 1; o <= 2; o <<= 1) {
            s1lo += __shfl_xor_sync(0xFFFFFFFFu, s1lo, o);
            s2lo += __shfl_xor_sync(0xFFFFFFFFu, s2lo, o);
            s1hi += __shfl_xor_sync(0xFFFFFFFFu, s1hi, o);
            s2hi += __shfl_xor_sync(0xFFFFFFFFu, s2hi, o);
        }
        if ((lane & 3) == 0) {
            int rloc = ma * 16 + (lane >> 2);
            sdS1[wid * 64 + rloc]     = s1lo;
            sdS2[wid * 64 + rloc]     = s2lo;
            sdS1[wid * 64 + rloc + 8] = s1hi;
            sdS2[wid * 64 + rloc + 8] = s2hi;
        }
    }
    __syncthreads();
    if (tid < TM) {
        int wrow = tid >> 6, rin = tid & 63;   // wrow: which warp-row (wr)
        float S1 = 0.f, S2 = 0.f;
#pragma unroll
        for (int w4 = 0; w4 < 4; w4++) {       // reduce across the 4 warp-cols
            S1 += sdS1[(wrow * 4 + w4) * 64 + rin];
            S2 += sdS2[(wrow * 4 + w4) * 64 + rin];
        }
        g_S1p[(size_t)vt * NTOK + m0 + tid] = S1;
        g_S2p[(size_t)vt * NTOK + m0 + tid] = S2;
    }
}

// ============================ kernel 3: tlogit + loss + final reduce =========
// block = (32 lanes, 32 warps) = 1024 threads; grid = 256 blocks of 32 tokens.
// Last block reduces all partials (fixed order) and resets cross-launch flags.
__global__ __launch_bounds__(1024) void loss_kernel(const void* __restrict__ tgt,
                                                    const float* __restrict__ bias,
                                                    float* __restrict__ out) {
    __shared__ float sh1[32][32];
    __shared__ float sh2[32][32];
    __shared__ float sh_tl[32];
    __shared__ int   islast;
    int tx = threadIdx.x;          // lane / token-in-block
    int ty = threadIdx.y;          // warp / vt-split
    int flag = g_tflag;

    // ---- Phase A: target logit for token (blockIdx.x*32 + ty), warp-per-token
    {
        int i = blockIdx.x * 32 + ty;
        int t = read_target(tgt, i, flag);
        const uint4* xv = (const uint4*)(g_Xbf + (size_t)i * DIM);   // 8 bf16 per uint4
        const uint4* wv = (const uint4*)(g_Wbf + (size_t)t * DIM);
        float acc = 0.0f;
#pragma unroll
        for (int j = 0; j < 4; j++) {
            uint4 av = xv[tx + 32 * j];
            uint4 bv = wv[tx + 32 * j];
            const __nv_bfloat162* a2 = (const __nv_bfloat162*)&av;
            const __nv_bfloat162* b2 = (const __nv_bfloat162*)&bv;
#pragma unroll
            for (int q = 0; q < 4; q++) {
                float2 af = __bfloat1622float2(a2[q]);
                float2 bf = __bfloat1622float2(b2[q]);
                acc = fmaf(af.x, bf.x, acc);
                acc = fmaf(af.y, bf.y, acc);
            }
        }
#pragma unroll
        for (int o = 16; o; o >>= 1) acc += __shfl_xor_sync(0xFFFFFFFFu, acc, o);
        if (tx == 0) sh_tl[ty] = acc + bias[t];
    }

    // ---- Phase B: vt-split partial sums (token tx, split ty)
    int i = blockIdx.x * 32 + tx;
    int vt0 = ty * 8;
    int vt1 = (vt0 + 8 < VT) ? vt0 + 8 : VT;   // last split (ty=31): 248..249
    float s1 = 0.0f, s2 = 0.0f;
#pragma unroll 8
    for (int vt = vt0; vt < vt1; vt++) {
        s1 += g_S1p[(size_t)vt * NTOK + i];
        s2 += g_S2p[(size_t)vt * NTOK + i];
    }
    sh1[ty][tx] = s1;
    sh2[ty][tx] = s2;
    __syncthreads();

    // ---- Phase C: per-token loss + deterministic global reduce
    if (ty == 0) {                 // one warp (tx = token 0..31)
        float S1 = 0.0f, S2 = 0.0f;
#pragma unroll
        for (int s = 0; s < 32; s++) { S1 += sh1[s][tx]; S2 += sh2[s][tx]; }
        int t = read_target(tgt, i, flag);
        float l = (t != 0)
            ? (logf(S1) - 0.9f * sh_tl[tx] - (0.1f / (float)VOC) * S2) : 0.0f;
        // fixed-order warp tree over the 32 tokens of this block
#pragma unroll
        for (int o = 16; o; o >>= 1) l += __shfl_xor_sync(0xFFFFFFFFu, l, o);
        if (tx == 0) {
            g_psum[blockIdx.x] = l;
            __threadfence();
            int old = atomicAdd(&g_bcount, 1);
            islast = (old == LOSS_BLOCKS - 1) ? 1 : 0;
        }
        __syncwarp();
        if (islast) {              // last block: reduce 256 partials, fixed order
            float a = 0.0f;
#pragma unroll
            for (int q = 0; q < LOSS_BLOCKS / 32; q++)   // each lane: 8 slots
                a += g_psum[tx * (LOSS_BLOCKS / 32) + q];
#pragma unroll
            for (int o = 16; o; o >>= 1) a += __shfl_xor_sync(0xFFFFFFFFu, a, o);
            if (tx == 0) out[0] = a;
        }
    }
    // ---- reset cross-launch flags for the next graph replay (last block only)
    __syncthreads();
    if (islast) {
        int tid1d = ty * 32 + tx;
        for (int q = tid1d; q < VT; q += 1024) g_wready[q] = 0;
        if (tid1d == 0) g_bcount = 0;
    }
}

// ============================ launch =========================================
extern "C" void kernel_launch(void* const* d_in, const int* in_sizes, int n_in,
                              void* d_out, int out_size) {
    const float* x    = (const float*)d_in[0];
    const void*  tgt  = d_in[1];
    const float* w    = (const float*)d_in[2];
    const float* bias = (const float*)d_in[3];

    cudaFuncSetAttribute(gemm_kernel, cudaFuncAttributeMaxDynamicSharedMemorySize, GEMM_SMEM);

    const size_t NPREP = NX4 + NW4HEAD;
    int pblocks = (int)((NPREP + 255) / 256);
    prep_kernel<<<pblocks, 256>>>(x, w, tgt);   // X + W head + detect + reset

    dim3 g(MT, VT);   // mt fast-varying: X tiles (16MB) stay resident in L2
    gemm_kernel<<<g, 256, GEMM_SMEM>>>(bias, w);  // look-ahead W convert inside

    loss_kernel<<<LOSS_BLOCKS, dim3(32, 32)>>>(tgt, bias, (float*)d_out);
}

// round 17
// speedup vs baseline: 1.9138x; 1.0046x over previous
#include <cuda_runtime.h>
#include <cuda_bf16.h>
#include <cstdint>

// ============================ problem constants =============================
static constexpr int NTOK = 8192;
static constexpr int DIM  = 1024;
static constexpr int VOC  = 32000;
static constexpr int TM = 128;            // tokens per CTA tile
static constexpr int TN = 128;            // vocab per CTA tile (2 CTAs/SM)
static constexpr int TK = 64;             // K elems per chunk (128B rows)
static constexpr int KCHUNKS = DIM / TK;  // 16
static constexpr int STAGES  = 3;
static constexpr int VT = VOC / TN;       // 250
static constexpr int MT = NTOK / TM;      // 64
static constexpr int LOSS_BLOCKS = 256;

// ============================ device scratch ================================
__device__ __align__(128) __nv_bfloat16 g_Xbf[(size_t)NTOK * DIM];   // 16 MB
__device__ __align__(128) __nv_bfloat16 g_Wbf[(size_t)VOC * DIM];    // 64 MB
__device__ __align__(128) float g_S1p[(size_t)VT * NTOK];            // 8 MB
__device__ __align__(128) float g_S2p[(size_t)VT * NTOK];            // 8 MB
__device__ __align__(128) float g_psum[LOSS_BLOCKS];
__device__ int g_tflag;   // 1 = target is int64, 0 = int32
__device__ int g_bcount;  // loss-block completion counter

// ============================ helpers =======================================
__device__ __forceinline__ uint32_t smem_u32(const void* p) {
    uint32_t a;
    asm("{ .reg .u64 t; cvta.to.shared.u64 t, %1; cvt.u32.u64 %0, t; }" : "=r"(a) : "l"(p));
    return a;
}
#define CP_ASYNC16(dst, src) \
    asm volatile("cp.async.cg.shared.global [%0], [%1], 16;" :: "r"(dst), "l"(src) : "memory")
#define CP_COMMIT() asm volatile("cp.async.commit_group;" ::: "memory")
#define CP_WAIT(n)  asm volatile("cp.async.wait_group %0;" :: "n"(n) : "memory")

__device__ __forceinline__ void ldm_x4(uint32_t* r, uint32_t addr) {
    asm volatile("ldmatrix.sync.aligned.m8n8.x4.shared.b16 {%0,%1,%2,%3}, [%4];"
        : "=r"(r[0]), "=r"(r[1]), "=r"(r[2]), "=r"(r[3]) : "r"(addr));
}
__device__ __forceinline__ void mma16816(float* c, const uint32_t* a, uint32_t b0, uint32_t b1) {
    asm volatile(
        "mma.sync.aligned.m16n8k16.row.col.f32.bf16.bf16.f32 "
        "{%0,%1,%2,%3}, {%4,%5,%6,%7}, {%8,%9}, {%0,%1,%2,%3};"
        : "+f"(c[0]), "+f"(c[1]), "+f"(c[2]), "+f"(c[3])
        : "r"(a[0]), "r"(a[1]), "r"(a[2]), "r"(a[3]), "r"(b0), "r"(b1));
}

// exp via MUFU: exp(x) = ex2(x * log2(e)); rel err ~2^-22
static constexpr float LOG2E = 1.4426950408889634f;
__device__ __forceinline__ float fexp2(float x) {
    float r;
    asm("ex2.approx.f32 %0, %1;" : "=f"(r) : "f"(x));
    return r;
}
__device__ __forceinline__ int read_target(const void* tgt, int i, int flag) {
    return flag ? (int)(((const long long*)tgt)[i]) : ((const int*)tgt)[i];
}
__device__ __forceinline__ uint32_t pack_bf162(float lo, float hi) {
    __nv_bfloat162 h = __floats2bfloat162_rn(lo, hi);
    return *(uint32_t*)&h;
}

// ============================ kernel 1: convert + dtype detect ===============
// vectorized: each thread reads 2x float4 (32B) and writes 1x uint4 (8 bf16).
// block 0 additionally scans target (dtype) and resets the loss counter.
static constexpr size_t NX8 = (size_t)NTOK * DIM / 8;
static constexpr size_t NW8 = (size_t)VOC * DIM / 8;
__global__ void convert_kernel(const float* __restrict__ x, const float* __restrict__ w,
                               const void* __restrict__ tgt) {
    if (blockIdx.x == 0) {
        __shared__ int bad;
        if (threadIdx.x == 0) { bad = 0; g_bcount = 0; }
        __syncthreads();
        const unsigned long long* p = (const unsigned long long*)tgt;
        for (int i = threadIdx.x; i < NTOK / 2; i += blockDim.x)
            if (p[i] >= (unsigned long long)VOC) bad = 1;
        __syncthreads();
        if (threadIdx.x == 0) g_tflag = bad ? 0 : 1;
    }
    size_t i = (size_t)blockIdx.x * blockDim.x + threadIdx.x;
    if (i < NX8) {
        const float4* s = (const float4*)x + 2 * i;
        float4 a = s[0], b = s[1];
        uint4 o;
        o.x = pack_bf162(a.x, a.y);
        o.y = pack_bf162(a.z, a.w);
        o.z = pack_bf162(b.x, b.y);
        o.w = pack_bf162(b.z, b.w);
        ((uint4*)g_Xbf)[i] = o;
    } else if (i < NX8 + NW8) {
        size_t j = i - NX8;
        const float4* s = (const float4*)w + 2 * j;
        float4 a = s[0], b = s[1];
        uint4 o;
        o.x = pack_bf162(a.x, a.y);
        o.y = pack_bf162(a.z, a.w);
        o.z = pack_bf162(b.x, b.y);
        o.w = pack_bf162(b.z, b.w);
        ((uint4*)g_Wbf)[j] = o;
    }
}

// ============================ kernel 2: GEMM + partial softmax ==============
// 2 CTAs per SM: CTA A's epilogue overlaps CTA B's MMA mainloop.
static constexpr int SM_BIAS   = 0;                       // 128 floats
static constexpr int SM_SRED1  = 512;                     // 8*64 floats
static constexpr int SM_SRED2  = 2560;
static constexpr int SM_STAGE0 = 5120;                    // 1024-aligned
static constexpr int A_BYTES   = TM * 128;                // 16384
static constexpr int STAGE_BYTES = (TM + TN) * 128;       // 32768
static constexpr int GEMM_SMEM = SM_STAGE0 + STAGES * STAGE_BYTES;  // 103424

__device__ __forceinline__ void load_chunk(uint32_t stage_base, int tid, int m0, int v0, int kc) {
    const __nv_bfloat16* Asrc = g_Xbf + (size_t)m0 * DIM + kc * TK;
    const __nv_bfloat16* Bsrc = g_Wbf + (size_t)v0 * DIM + kc * TK;
#pragma unroll
    for (int i = 0; i < 8; i++) {
        int g = tid + i * 256;                 // 0..2047
        if (g < 1024) {                        // A: 128 rows x 8 x 16B
            int row = g >> 3, c16 = g & 7;
            uint32_t off = (uint32_t)(row * 128) + (((uint32_t)c16 * 16) ^ (((uint32_t)row & 7) << 4));
            CP_ASYNC16(stage_base + off, Asrc + (size_t)row * DIM + c16 * 8);
        } else {                               // B: 128 rows x 8 x 16B
            int g2 = g - 1024;
            int row = g2 >> 3, c16 = g2 & 7;
            uint32_t off = (uint32_t)(row * 128) + (((uint32_t)c16 * 16) ^ (((uint32_t)row & 7) << 4));
            CP_ASYNC16(stage_base + A_BYTES + off, Bsrc + (size_t)row * DIM + c16 * 8);
        }
    }
}

__global__ __launch_bounds__(256, 2) void gemm_kernel(const float* __restrict__ bias) {
    extern __shared__ char smem[];
    uint32_t sb = smem_u32(smem);
    int tid = threadIdx.x;
    int lane = tid & 31, wid = tid >> 5;
    int wr = wid >> 2, wc = wid & 3;           // warp row (M: 2x64), warp col (N: 4x32)
    int mt = blockIdx.x, vt = blockIdx.y;
    int m0 = mt * TM, v0 = vt * TN;

    float* biasS = (float*)(smem + SM_BIAS);
    float* sdS1  = (float*)(smem + SM_SRED1);  // [8 warps][64 rows]
    float* sdS2  = (float*)(smem + SM_SRED2);
    if (tid < TN) biasS[tid] = bias[v0 + tid];

    // ldmatrix per-lane geometry (offsets within a stage)
    uint32_t xm    = ((uint32_t)lane & 7) << 4;
    int arow  = wr * 64 + (lane & 7) + ((lane >> 3) & 1) * 8;
    uint32_t acolt = ((uint32_t)(lane >> 4) & 1) * 16;
    int brow  = wc * 32 + ((lane >> 4) & 1) * 8 + (lane & 7);
    uint32_t bcolt = ((uint32_t)(lane >> 3) & 1) * 16;

    float acc[4][4][4];                        // 64 accums/thread
#pragma unroll
    for (int i = 0; i < 4; i++)
#pragma unroll
        for (int j = 0; j < 4; j++)
#pragma unroll
            for (int k = 0; k < 4; k++) acc[i][j][k] = 0.0f;

    // prologue: fill stages 0..1
#pragma unroll
    for (int s = 0; s < STAGES - 1; s++) {
        load_chunk(sb + SM_STAGE0 + s * STAGE_BYTES, tid, m0, v0, s);
        CP_COMMIT();
    }

    int st_c = 0, st_l = STAGES - 1;           // rotating stage indices
    for (int kc = 0; kc < KCHUNKS; kc++) {
        CP_WAIT(1);
        __syncthreads();
        if (kc + STAGES - 1 < KCHUNKS)
            load_chunk(sb + SM_STAGE0 + st_l * STAGE_BYTES, tid, m0, v0, kc + STAGES - 1);
        CP_COMMIT();   // fixed group cadence
        if (++st_l == STAGES) st_l = 0;

        uint32_t abase = sb + SM_STAGE0 + st_c * STAGE_BYTES;
        uint32_t bbase = abase + A_BYTES;
        if (++st_c == STAGES) st_c = 0;
#pragma unroll
        for (int s = 0; s < 4; s++) {          // 4 k16-steps per 64-elem chunk
            uint32_t a[4][4], b[2][4];
#pragma unroll
            for (int ma = 0; ma < 4; ma++)
                ldm_x4(a[ma], abase + (uint32_t)((arow + ma * 16) * 128) + (((uint32_t)(s * 32) + acolt) ^ xm));
#pragma unroll
            for (int p = 0; p < 2; p++)
                ldm_x4(b[p], bbase + (uint32_t)((brow + p * 16) * 128) + (((uint32_t)(s * 32) + bcolt) ^ xm));
#pragma unroll
            for (int ma = 0; ma < 4; ma++)
#pragma unroll
                for (int na = 0; na < 4; na++)
                    mma16816(acc[ma][na], a[ma], b[na >> 1][(na & 1) * 2], b[na >> 1][(na & 1) * 2 + 1]);
        }
    }
    __syncthreads();

    // ---- fused epilogue: bias + MUFU exp + row reduction ----
#pragma unroll
    for (int ma = 0; ma < 4; ma++) {
        float s1lo = 0.f, s2lo = 0.f, s1hi = 0.f, s2hi = 0.f;
#pragma unroll
        for (int na = 0; na < 4; na++) {
            int c0 = wc * 32 + na * 8 + 2 * (lane & 3);
            float b0 = biasS[c0], b1 = biasS[c0 + 1];
            float v;
            v = acc[ma][na][0] + b0; s2lo += v; s1lo += fexp2(v * LOG2E);
            v = acc[ma][na][1] + b1; s2lo += v; s1lo += fexp2(v * LOG2E);
            v = acc[ma][na][2] + b0; s2hi += v; s1hi += fexp2(v * LOG2E);
            v = acc[ma][na][3] + b1; s2hi += v; s1hi += fexp2(v * LOG2E);
        }
#pragma unroll
        for (int o = 1; o <= 2; o <<= 1) {
            s1lo += __shfl_xor_sync(0xFFFFFFFFu, s1lo, o);
            s2lo += __shfl_xor_sync(0xFFFFFFFFu, s2lo, o);
            s1hi += __shfl_xor_sync(0xFFFFFFFFu, s1hi, o);
            s2hi += __shfl_xor_sync(0xFFFFFFFFu, s2hi, o);
        }
        if ((lane & 3) == 0) {
            int rloc = ma * 16 + (lane >> 2);
            sdS1[wid * 64 + rloc]     = s1lo;
            sdS2[wid * 64 + rloc]     = s2lo;
            sdS1[wid * 64 + rloc + 8] = s1hi;
            sdS2[wid * 64 + rloc + 8] = s2hi;
        }
    }
    __syncthreads();
    if (tid < TM) {
        int wrow = tid >> 6, rin = tid & 63;   // wrow: which warp-row (wr)
        float S1 = 0.f, S2 = 0.f;
#pragma unroll
        for (int w4 = 0; w4 < 4; w4++) {       // reduce across the 4 warp-cols
            S1 += sdS1[(wrow * 4 + w4) * 64 + rin];
            S2 += sdS2[(wrow * 4 + w4) * 64 + rin];
        }
        g_S1p[(size_t)vt * NTOK + m0 + tid] = S1;
        g_S2p[(size_t)vt * NTOK + m0 + tid] = S2;
    }
}

// ============================ kernel 3: tlogit + loss + final reduce =========
// block = (32 lanes, 32 warps) = 1024 threads; grid = 256 blocks of 32 tokens.
// Phase A: warp ty computes the target logit of token ty (bf16 dot).
// Phase B: thread (tx,ty) = (token, vt-split) partial S1/S2 sums.
// Phase C: warp 0 computes per-token loss + block sum; last block reduces all.
__global__ __launch_bounds__(1024) void loss_kernel(const void* __restrict__ tgt,
                                                    const float* __restrict__ bias,
                                                    float* __restrict__ out) {
    __shared__ float sh1[32][32];
    __shared__ float sh2[32][32];
    __shared__ float sh_tl[32];
    __shared__ int   islast;
    int tx = threadIdx.x;          // lane / token-in-block
    int ty = threadIdx.y;          // warp / vt-split
    int flag = g_tflag;

    // ---- Phase A: target logit for token (blockIdx.x*32 + ty), warp-per-token
    {
        int i = blockIdx.x * 32 + ty;
        int t = read_target(tgt, i, flag);
        const uint4* xv = (const uint4*)(g_Xbf + (size_t)i * DIM);   // 8 bf16 per uint4
        const uint4* wv = (const uint4*)(g_Wbf + (size_t)t * DIM);
        float acc = 0.0f;
#pragma unroll
        for (int j = 0; j < 4; j++) {
            uint4 av = xv[tx + 32 * j];
            uint4 bv = wv[tx + 32 * j];
            const __nv_bfloat162* a2 = (const __nv_bfloat162*)&av;
            const __nv_bfloat162* b2 = (const __nv_bfloat162*)&bv;
#pragma unroll
            for (int q = 0; q < 4; q++) {
                float2 af = __bfloat1622float2(a2[q]);
                float2 bf = __bfloat1622float2(b2[q]);
                acc = fmaf(af.x, bf.x, acc);
                acc = fmaf(af.y, bf.y, acc);
            }
        }
#pragma unroll
        for (int o = 16; o; o >>= 1) acc += __shfl_xor_sync(0xFFFFFFFFu, acc, o);
        if (tx == 0) sh_tl[ty] = acc + bias[t];
    }

    // ---- Phase B: vt-split partial sums (token tx, split ty)
    int i = blockIdx.x * 32 + tx;
    int vt0 = ty * 8;
    int vt1 = (vt0 + 8 < VT) ? vt0 + 8 : VT;   // last split (ty=31): 248..249
    float s1 = 0.0f, s2 = 0.0f;
#pragma unroll 8
    for (int vt = vt0; vt < vt1; vt++) {
        s1 += g_S1p[(size_t)vt * NTOK + i];
        s2 += g_S2p[(size_t)vt * NTOK + i];
    }
    sh1[ty][tx] = s1;
    sh2[ty][tx] = s2;
    __syncthreads();

    // ---- Phase C: per-token loss + deterministic global reduce
    if (ty == 0) {                 // one warp (tx = token 0..31)
        float S1 = 0.0f, S2 = 0.0f;
#pragma unroll
        for (int s = 0; s < 32; s++) { S1 += sh1[s][tx]; S2 += sh2[s][tx]; }
        int t = read_target(tgt, i, flag);
        float l = (t != 0)
            ? (logf(S1) - 0.9f * sh_tl[tx] - (0.1f / (float)VOC) * S2) : 0.0f;
        // fixed-order warp tree over the 32 tokens of this block
#pragma unroll
        for (int o = 16; o; o >>= 1) l += __shfl_xor_sync(0xFFFFFFFFu, l, o);
        if (tx == 0) {
            g_psum[blockIdx.x] = l;
            __threadfence();
            int old = atomicAdd(&g_bcount, 1);
            islast = (old == LOSS_BLOCKS - 1) ? 1 : 0;
        }
        __syncwarp();
        if (islast) {              // last block: reduce 256 partials, fixed order
            float a = 0.0f;
#pragma unroll
            for (int q = 0; q < LOSS_BLOCKS / 32; q++)   // each lane: 8 slots
                a += g_psum[tx * (LOSS_BLOCKS / 32) + q];
#pragma unroll
            for (int o = 16; o; o >>= 1) a += __shfl_xor_sync(0xFFFFFFFFu, a, o);
            if (tx == 0) out[0] = a;
        }
    }
}

// ============================ launch =========================================
extern "C" void kernel_launch(void* const* d_in, const int* in_sizes, int n_in,
                              void* d_out, int out_size) {
    const float* x    = (const float*)d_in[0];
    const void*  tgt  = d_in[1];
    const float* w    = (const float*)d_in[2];
    const float* bias = (const float*)d_in[3];

    cudaFuncSetAttribute(gemm_kernel, cudaFuncAttributeMaxDynamicSharedMemorySize, GEMM_SMEM);

    const size_t NCONV = NX8 + NW8;
    int cblocks = (int)((NCONV + 255) / 256);
    convert_kernel<<<cblocks, 256>>>(x, w, tgt);   // includes dtype detect + counter reset

    dim3 g(MT, VT);   // mt fast-varying: X tiles (16MB) stay resident in L2
    gemm_kernel<<<g, 256, GEMM_SMEM>>>(bias);

    loss_kernel<<<LOSS_BLOCKS, dim3(32, 32)>>>(tgt, bias, (float*)d_out);
}